// round 13
// baseline (speedup 1.0000x reference)
#include <cuda_runtime.h>
#include <cuda_fp16.h>
#include <cstdint>

#define NROW 12288
#define INF  128
#define OUTF 64
#define LOG2E 1.44269504088896341f
#define NCHUNK 3
#define CT 32                      // tiles per chunk (32*128 = 4096 cols)
#define NITILE (NROW / 128)        // 96
#define NUNITS (NITILE * NCHUNK)   // 288 == grid
#define KCMAX (CT * 4)             // 128 k-chunks per warp per unit (k-split halves)

// smem offsets
#define B0o  0
#define B1o  16384
#define WH2S 32768
#define SMEM_BYTES 49152

// ---------------- device scratch ----------------
__device__ float  g_wh1[NROW];
__device__ float  g_wh2[NROW];
__device__ float  g_wh2max;
// h transposed fp16 [f][j], with j PRE-PERMUTED into mma k-slot order:
// within each 16-j group, j=16g+4c+e -> half-pos p=16g+2c+e (e<2) / 16g+8+2c+(e-2)
__device__ __align__(16) __half g_hTp[OUTF * NROW];
__device__ float  g_S[NCHUNK][NROW * OUTF];          // partial E'@h per chunk
__device__ float  g_L[NCHUNK][NROW];                 // row sums per chunk

// ---------------- Kernel A: h = input@W, wh1/wh2, permuted hT ----------------
__global__ void kA(const float* __restrict__ inp, const float* __restrict__ W,
                   const float* __restrict__ a) {
    __shared__ float in_s[4][INF];
    __shared__ float red1[8], red2[8];
    int tid = threadIdx.x;
    int i0 = blockIdx.x * 4;
    for (int e = tid; e < 4 * INF; e += 256)
        in_s[e >> 7][e & 127] = inp[(i0 + (e >> 7)) * INF + (e & 127)];
    __syncthreads();
    int f = tid & 63, r = tid >> 6;
    float acc = 0.f;
#pragma unroll 8
    for (int k = 0; k < INF; k++)
        acc = fmaf(in_s[r][k], W[k * OUTF + f], acc);
    int i = i0 + r;
    {   // permuted position
        int g = i >> 4, rr = i & 15;
        int c = rr >> 2, e = rr & 3;
        int p = g * 16 + ((e < 2) ? (2 * c + e) : (8 + 2 * c + (e - 2)));
        g_hTp[f * NROW + p] = __float2half(acc);
    }
    float p1 = acc * a[f];
    float p2 = acc * a[64 + f];
#pragma unroll
    for (int o = 16; o > 0; o >>= 1) {
        p1 += __shfl_xor_sync(~0u, p1, o);
        p2 += __shfl_xor_sync(~0u, p2, o);
    }
    int w = tid >> 5;
    if ((tid & 31) == 0) { red1[w] = p1; red2[w] = p2; }
    __syncthreads();
    if (tid < 4) {
        g_wh1[i0 + tid] = red1[2 * tid] + red1[2 * tid + 1];
        g_wh2[i0 + tid] = red2[2 * tid] + red2[2 * tid + 1];
    }
}

// ---------------- Kernel A2: global max of wh2 ----------------
__global__ void kMax() {
    __shared__ float red[8];
    int tid = threadIdx.x;
    float m = -1e30f;
    for (int i = tid; i < NROW; i += 256) m = fmaxf(m, g_wh2[i]);
#pragma unroll
    for (int o = 16; o > 0; o >>= 1) m = fmaxf(m, __shfl_xor_sync(~0u, m, o));
    if ((tid & 31) == 0) red[tid >> 5] = m;
    __syncthreads();
    if (tid == 0) {
        float mm = red[0];
#pragma unroll
        for (int w = 1; w < 8; w++) mm = fmaxf(mm, red[w]);
        g_wh2max = mm;
    }
}

// pad so ncu's capture (launch index 3) lands on kMain
__global__ void kPad() {}

__device__ __forceinline__ void cp_async16(uint32_t dst, const void* src) {
    asm volatile("cp.async.cg.shared.global [%0], [%1], 16;\n" :: "r"(dst), "l"(src));
}

// ---------------- Kernel B: k-split warp pairs, cp.async B, reg A-fragments ----------------
// 256 threads, 2 CTAs/SM. Warp pair p=(w>>1) owns rows i0+p*32..+31; half hf=(w&1)
// covers k-slots (j's) hf*64..hf*64+63 of each 128-j tile. Partials merged per unit.
__global__ void __launch_bounds__(256, 2) kMain(const int* __restrict__ adj) {
    extern __shared__ char smem[];
    uint32_t sb = (uint32_t)__cvta_generic_to_shared(smem);
    float* wh2s = (float*)(smem + WH2S);
    int tid = threadIdx.x, lane = tid & 31, w = tid >> 5;
    int p = w >> 1, hf = w & 1;

    int u = blockIdx.x;
    int itile = u / NCHUNK, chunk = u % NCHUNK;
    int i0 = itile * 128;
    long long jbase = (long long)chunk * (CT * 128);

    // stage this unit's wh2 (4096 floats = 16KB)
    {
        const float4* src = (const float4*)(g_wh2 + jbase);
        float4* dst = (float4*)wh2s;
#pragma unroll
        for (int k = 0; k < 4; k++) dst[tid + k * 256] = src[tid + k * 256];
    }

    // cp.async B mapping: thread -> row n=tid>>2, 4 x 16B units u0..u0+3
    int bn = tid >> 2;
    int bu0 = (tid & 3) * 4;
    uint32_t bnx = (uint32_t)((bn & 7) << 1);
    const char* bsrc = (const char*)g_hTp + ((size_t)bn * NROW + (size_t)jbase) * 2 + bu0 * 16;
    uint32_t bdst_row = (uint32_t)(bn * 256);
    // prologue: fill buf0 (tile 0)
#pragma unroll
    for (int k = 0; k < 4; k++)
        cp_async16(sb + B0o + bdst_row + ((uint32_t)((bu0 + k) ^ bnx) << 4), bsrc + k * 16);
    asm volatile("cp.async.commit_group;");

    // per-lane row constants (rows rA + 8s, s=0..3)
    int rA = i0 + p * 32 + (lane >> 2);
    const float wh2max = g_wh2max;
    float w1r[4], m2r[4], fr[4];
#pragma unroll
    for (int s = 0; s < 4; s++) {
        float w1 = g_wh1[rA + 8 * s];
        float sA = w1 + wh2max;
        w1r[s] = w1;
        m2r[s] = fmaxf(sA, 0.2f * sA) * LOG2E;   // lrelu upper bound of row max
        fr[s] = 0.f;
    }

    // adj stream: lane covers j = (tile,kc) base + jh + (lane&3)*4 .. +3
    int jh = hf * 64;
    const int* pAdj = adj + (long long)rA * NROW + jbase + jh + (lane & 3) * 4;
    int4 avv[2][4];
#pragma unroll
    for (int s = 0; s < 4; s++) {
        avv[0][s] = __ldcs((const int4*)(pAdj + 8LL * s * NROW));
        avv[1][s] = __ldcs((const int4*)(pAdj + 8LL * s * NROW + 16));
    }

    // B ldmatrix constants (R7-proven pattern)
    int g2 = lane >> 4, kh = (lane >> 3) & 1, r7 = lane & 7;
    uint32_t bxor = (uint32_t)(r7 << 1);
    uint32_t Bb2off = (uint32_t)((g2 * 8 + r7) * 256);

    float acc[2][8][4];
#pragma unroll
    for (int mt = 0; mt < 2; mt++)
#pragma unroll
        for (int nt = 0; nt < 8; nt++)
#pragma unroll
            for (int q = 0; q < 4; q++) acc[mt][nt][q] = 0.f;

    __syncthreads();   // wh2s staged

    for (int t = 0; t < CT; t++) {
        uint32_t Bbuf = sb + ((t & 1) ? B1o : B0o);
        asm volatile("cp.async.wait_group 0;");
        __syncthreads();    // B(t) visible everywhere; all warps done reading B(t-1)'s buffer

        if (t + 1 < CT) {   // prefetch B(t+1) into the other buffer
            const char* src = bsrc + (t + 1) * 256;
            uint32_t dstb = sb + (((t + 1) & 1) ? B1o : B0o) + bdst_row;
#pragma unroll
            for (int k = 0; k < 4; k++)
                cp_async16(dstb + ((uint32_t)((bu0 + k) ^ bnx) << 4), src + k * 16);
            asm volatile("cp.async.commit_group;");
        }

#pragma unroll
        for (int kc = 0; kc < 4; kc++) {
            int kcg = t * 4 + kc;
            int b = kcg & 1;
            int off2 = ((kcg + 2) >> 2) * 128 + ((kcg + 2) & 3) * 16;
            float4 wv = *(const float4*)(wh2s + t * 128 + jh + kc * 16 + (lane & 3) * 4);

            uint32_t af[8];
#pragma unroll
            for (int s = 0; s < 4; s++) {
                int4 av = avv[b][s];
                float w1 = w1r[s], m2 = m2r[s];
                float s0 = w1 + wv.x, s1 = w1 + wv.y, s2 = w1 + wv.z, s3 = w1 + wv.w;
                float x0 = fmaf(fmaxf(s0, 0.2f * s0), LOG2E, -m2);
                float x1 = fmaf(fmaxf(s1, 0.2f * s1), LOG2E, -m2);
                float x2 = fmaf(fmaxf(s2, 0.2f * s2), LOG2E, -m2);
                float x3 = fmaf(fmaxf(s3, 0.2f * s3), LOG2E, -m2);
                x0 = av.x ? x0 : -1e4f;
                x1 = av.y ? x1 : -1e4f;
                x2 = av.z ? x2 : -1e4f;
                x3 = av.w ? x3 : -1e4f;
                if (kcg + 2 < KCMAX)   // rolling depth-2 prefetch (per-stream, low overlap)
                    avv[b][s] = __ldcs((const int4*)(pAdj + 8LL * s * NROW + off2));
                __half2 h01 = __floats2half2_rn(x0, x1);
                __half2 h23 = __floats2half2_rn(x2, x3);
                uint32_t e01, e23;
                asm("ex2.approx.f16x2 %0, %1;" : "=r"(e01) : "r"(*(uint32_t*)&h01));
                asm("ex2.approx.f16x2 %0, %1;" : "=r"(e23) : "r"(*(uint32_t*)&h23));
                // af slots: s0->(0,2) s1->(1,3) s2->(4,6) s3->(5,7)
                int lo = (s & 2) * 2 + (s & 1);
                af[lo] = e01;
                af[lo + 2] = e23;
                __half2 hs = __hadd2(*(__half2*)&e01, *(__half2*)&e23);
                float2 fs = __half22float2(hs);
                fr[s] += fs.x + fs.y;
            }

            uint32_t bsw = (((uint32_t)((hf * 4 + kc) * 2 + kh)) ^ bxor) << 4;
            uint32_t Bb = Bbuf + Bb2off + bsw;
#pragma unroll
            for (int nt2 = 0; nt2 < 4; nt2++) {
                uint32_t b0, b1, b2, b3;
                asm volatile("ldmatrix.sync.aligned.m8n8.x4.shared.b16 {%0,%1,%2,%3}, [%4];"
                             : "=r"(b0), "=r"(b1), "=r"(b2), "=r"(b3)
                             : "r"(Bb + (uint32_t)(nt2 * 4096)));
                int nt = nt2 * 2;
                asm volatile("mma.sync.aligned.m16n8k16.row.col.f32.f16.f16.f32 "
                             "{%0,%1,%2,%3}, {%4,%5,%6,%7}, {%8,%9}, {%0,%1,%2,%3};"
                             : "+f"(acc[0][nt][0]), "+f"(acc[0][nt][1]),
                               "+f"(acc[0][nt][2]), "+f"(acc[0][nt][3])
                             : "r"(af[0]), "r"(af[1]), "r"(af[2]), "r"(af[3]), "r"(b0), "r"(b1));
                asm volatile("mma.sync.aligned.m16n8k16.row.col.f32.f16.f16.f32 "
                             "{%0,%1,%2,%3}, {%4,%5,%6,%7}, {%8,%9}, {%0,%1,%2,%3};"
                             : "+f"(acc[0][nt + 1][0]), "+f"(acc[0][nt + 1][1]),
                               "+f"(acc[0][nt + 1][2]), "+f"(acc[0][nt + 1][3])
                             : "r"(af[0]), "r"(af[1]), "r"(af[2]), "r"(af[3]), "r"(b2), "r"(b3));
                asm volatile("mma.sync.aligned.m16n8k16.row.col.f32.f16.f16.f32 "
                             "{%0,%1,%2,%3}, {%4,%5,%6,%7}, {%8,%9}, {%0,%1,%2,%3};"
                             : "+f"(acc[1][nt][0]), "+f"(acc[1][nt][1]),
                               "+f"(acc[1][nt][2]), "+f"(acc[1][nt][3])
                             : "r"(af[4]), "r"(af[5]), "r"(af[6]), "r"(af[7]), "r"(b0), "r"(b1));
                asm volatile("mma.sync.aligned.m16n8k16.row.col.f32.f16.f16.f32 "
                             "{%0,%1,%2,%3}, {%4,%5,%6,%7}, {%8,%9}, {%0,%1,%2,%3};"
                             : "+f"(acc[1][nt + 1][0]), "+f"(acc[1][nt + 1][1]),
                               "+f"(acc[1][nt + 1][2]), "+f"(acc[1][nt + 1][3])
                             : "r"(af[4]), "r"(af[5]), "r"(af[6]), "r"(af[7]), "r"(b2), "r"(b3));
            }
        }
    }

    // ---------------- pair merge + writeback ----------------
    __syncthreads();   // all ldmatrix done; B buffers reusable as exchange space
    float* exch = (float*)smem;                 // 32 KB: 4 pairs x 8 KB
    float* frx = (float*)(smem + WH2S);         // row-sum exchange
    // quad-reduce row sums (each warp: rows rA+8s summed over its 4 j's)
#pragma unroll
    for (int s = 0; s < 4; s++) {
        fr[s] += __shfl_xor_sync(~0u, fr[s], 1);
        fr[s] += __shfl_xor_sync(~0u, fr[s], 2);
    }
    if (hf == 1) {
        float* dst = exch + p * 2048;
#pragma unroll
        for (int mt = 0; mt < 2; mt++)
#pragma unroll
            for (int nt = 0; nt < 8; nt++)
#pragma unroll
                for (int q = 0; q < 4; q++)
                    dst[((mt * 8 + nt) * 4 + q) * 32 + lane] = acc[mt][nt][q];
        if ((lane & 3) == 0) {
#pragma unroll
            for (int s = 0; s < 4; s++)
                frx[p * 32 + (lane >> 2) + 8 * s] = fr[s];
        }
    }
    __syncthreads();
    if (hf == 0) {
        const float* src = exch + p * 2048;
        float* Sp = g_S[chunk];
        int g = lane >> 2, tq = lane & 3;
#pragma unroll
        for (int mt = 0; mt < 2; mt++)
#pragma unroll
            for (int nt = 0; nt < 8; nt++) {
                int c = (mt * 8 + nt) * 4;
                float a0 = acc[mt][nt][0] + src[(c + 0) * 32 + lane];
                float a1 = acc[mt][nt][1] + src[(c + 1) * 32 + lane];
                float a2 = acc[mt][nt][2] + src[(c + 2) * 32 + lane];
                float a3 = acc[mt][nt][3] + src[(c + 3) * 32 + lane];
                int row0 = i0 + p * 32 + mt * 16 + g;
                int col = nt * 8 + tq * 2;
                *(float2*)(Sp + row0 * OUTF + col) = make_float2(a0, a1);
                *(float2*)(Sp + (row0 + 8) * OUTF + col) = make_float2(a2, a3);
            }
        if ((lane & 3) == 0) {
#pragma unroll
            for (int s = 0; s < 4; s++)
                g_L[chunk][rA + 8 * s] = fr[s] + frx[p * 32 + (lane >> 2) + 8 * s];
        }
    }
}

// ---------------- Kernel C: reduce chunks, normalize + ELU ----------------
__global__ void kEpi(float* __restrict__ out) {
    int idx = blockIdx.x * 256 + threadIdx.x;   // NROW*64
    int i = idx >> 6, f = idx & 63;
    float l = 0.f, v = 0.f;
#pragma unroll
    for (int c = 0; c < NCHUNK; c++) {
        l += g_L[c][i];
        v += g_S[c][i * OUTF + f];
    }
    v /= l;
    out[idx] = v > 0.f ? v : expm1f(v);
}

// ---------------- launch ----------------
extern "C" void kernel_launch(void* const* d_in, const int* in_sizes, int n_in,
                              void* d_out, int out_size) {
    (void)in_sizes; (void)n_in; (void)out_size;
    const float* inp = (const float*)d_in[0];
    const int*   adj = (const int*)d_in[1];
    const float* W   = (const float*)d_in[2];
    const float* a   = (const float*)d_in[3];

    cudaFuncSetAttribute(kMain, cudaFuncAttributeMaxDynamicSharedMemorySize, SMEM_BYTES);

    kA<<<NROW / 4, 256>>>(inp, W, a);           // index 0
    kMax<<<1, 256>>>();                         // index 1
    kPad<<<1, 32>>>();                          // index 2
    kMain<<<NUNITS, 256, SMEM_BYTES>>>(adj);    // index 3  <- ncu capture
    kEpi<<<NROW * OUTF / 256, 256>>>((float*)d_out);
}

// round 15
// speedup vs baseline: 1.1366x; 1.1366x over previous
#include <cuda_runtime.h>
#include <cuda_fp16.h>
#include <cstdint>

#define NROW 12288
#define INF  128
#define OUTF 64
#define LOG2E 1.44269504088896341f
#define NCHUNK 6
#define CT 16                      // tiles per chunk (16*128 = 2048 cols)
#define NITILE (NROW / 256)        // 48 (256-row i-tiles)
#define NUNITS (NITILE * NCHUNK)   // 288 == grid
#define KCMAX (CT * 8)             // 128 k-chunks per unit

// smem offsets
#define B0o  0
#define B1o  16384
#define WH2S 32768
#define SMEM_BYTES 40960

// ---------------- device scratch ----------------
__device__ float  g_wh1[NROW];
__device__ float  g_wh2[NROW];
__device__ float  g_wh2max;
// h transposed fp16 [f][j], j PRE-PERMUTED into mma k-slot order:
// within each 16-j group, j=16g+4c+e -> p=16g+2c+e (e<2) / 16g+8+2c+(e-2)
__device__ __align__(16) __half g_hTp[OUTF * NROW];
__device__ float  g_S[NCHUNK][NROW * OUTF];          // partial E'@h per chunk
__device__ float  g_L[NCHUNK][NROW];                 // row sums per chunk

// ---------------- Kernel A: h = input@W, wh1/wh2, permuted hT ----------------
__global__ void kA(const float* __restrict__ inp, const float* __restrict__ W,
                   const float* __restrict__ a) {
    __shared__ float in_s[4][INF];
    __shared__ float red1[8], red2[8];
    int tid = threadIdx.x;
    int i0 = blockIdx.x * 4;
    for (int e = tid; e < 4 * INF; e += 256)
        in_s[e >> 7][e & 127] = inp[(i0 + (e >> 7)) * INF + (e & 127)];
    __syncthreads();
    int f = tid & 63, r = tid >> 6;
    float acc = 0.f;
#pragma unroll 8
    for (int k = 0; k < INF; k++)
        acc = fmaf(in_s[r][k], W[k * OUTF + f], acc);
    int i = i0 + r;
    {   // permuted position
        int g = i >> 4, rr = i & 15;
        int c = rr >> 2, e = rr & 3;
        int p = g * 16 + ((e < 2) ? (2 * c + e) : (8 + 2 * c + (e - 2)));
        g_hTp[f * NROW + p] = __float2half(acc);
    }
    float p1 = acc * a[f];
    float p2 = acc * a[64 + f];
#pragma unroll
    for (int o = 16; o > 0; o >>= 1) {
        p1 += __shfl_xor_sync(~0u, p1, o);
        p2 += __shfl_xor_sync(~0u, p2, o);
    }
    int w = tid >> 5;
    if ((tid & 31) == 0) { red1[w] = p1; red2[w] = p2; }
    __syncthreads();
    if (tid < 4) {
        g_wh1[i0 + tid] = red1[2 * tid] + red1[2 * tid + 1];
        g_wh2[i0 + tid] = red2[2 * tid] + red2[2 * tid + 1];
    }
}

// ---------------- Kernel A2: global max of wh2 ----------------
__global__ void kMax() {
    __shared__ float red[8];
    int tid = threadIdx.x;
    float m = -1e30f;
    for (int i = tid; i < NROW; i += 256) m = fmaxf(m, g_wh2[i]);
#pragma unroll
    for (int o = 16; o > 0; o >>= 1) m = fmaxf(m, __shfl_xor_sync(~0u, m, o));
    if ((tid & 31) == 0) red[tid >> 5] = m;
    __syncthreads();
    if (tid == 0) {
        float mm = red[0];
#pragma unroll
        for (int w = 1; w < 8; w++) mm = fmaxf(mm, red[w]);
        g_wh2max = mm;
    }
}

// pad so ncu's capture (launch index 3) lands on kMain
__global__ void kPad() {}

__device__ __forceinline__ void cp_async16(uint32_t dst, const void* src) {
    asm volatile("cp.async.cg.shared.global [%0], [%1], 16;\n" :: "r"(dst), "l"(src));
}

// ---------------- Kernel B: 256-row i-tiles, M=32/warp, cp.async B ----------------
// 256 threads, 2 CTAs/SM. Warp w owns rows i0 + w*32 .. +31 (4 streams of 8 rows),
// all k-slots of every tile. Each B fragment feeds 2 m-tiles (halved B-LDSM/byte).
__global__ void __launch_bounds__(256, 2) kMain(const int* __restrict__ adj) {
    extern __shared__ char smem[];
    uint32_t sb = (uint32_t)__cvta_generic_to_shared(smem);
    float* wh2s = (float*)(smem + WH2S);
    int tid = threadIdx.x, lane = tid & 31, w = tid >> 5;

    int u = blockIdx.x;
    int itile = u / NCHUNK, chunk = u % NCHUNK;
    int i0 = itile * 256;
    long long jbase = (long long)chunk * (CT * 128);

    // stage this unit's wh2 (2048 floats = 8KB)
    {
        const float4* src = (const float4*)(g_wh2 + jbase);
        float4* dst = (float4*)wh2s;
        dst[tid] = src[tid];
        dst[tid + 256] = src[tid + 256];
    }

    // cp.async B mapping (R8-proven): thread -> row bn=tid>>2, 4 x 16B units
    int bn = tid >> 2;
    int bu0 = (tid & 3) * 4;
    uint32_t bnx = (uint32_t)((bn & 7) << 1);
    const char* bsrc = (const char*)g_hTp + ((size_t)bn * NROW + (size_t)jbase) * 2 + bu0 * 16;
    uint32_t bdst_row = (uint32_t)(bn * 256);
#pragma unroll
    for (int k = 0; k < 4; k++)
        cp_async16(sb + B0o + bdst_row + ((uint32_t)((bu0 + k) ^ bnx) << 4), bsrc + k * 16);
    asm volatile("cp.async.commit_group;");

    // per-lane row constants (rows rA + 8s, s=0..3)
    int rA = i0 + w * 32 + (lane >> 2);
    const float wh2max = g_wh2max;
    float w1r[4], m2r[4], fr[4];
#pragma unroll
    for (int s = 0; s < 4; s++) {
        float w1 = g_wh1[rA + 8 * s];
        float sA = w1 + wh2max;
        w1r[s] = w1;
        m2r[s] = fmaxf(sA, 0.2f * sA) * LOG2E;   // lrelu upper bound of row max
        fr[s] = 0.f;
    }

    // adj streams: lane covers j = jbase + kc*16 + (lane&3)*4 .. +3, rows rA+8s
    const int* pAdj = adj + (long long)rA * NROW + jbase + (lane & 3) * 4;
    // prefetch clamp: reads of kc >= KCMAX are redirected to kc=0 (harmless, in-bounds)
    int4 avv[2][4];
#pragma unroll
    for (int s = 0; s < 4; s++) {
        avv[0][s] = __ldcs((const int4*)(pAdj + 8LL * s * NROW));
        avv[1][s] = __ldcs((const int4*)(pAdj + 8LL * s * NROW + 16));
    }

    // B ldmatrix constants (R10-proven)
    int g2 = lane >> 4, kh = (lane >> 3) & 1, r7 = lane & 7;
    uint32_t bxor = (uint32_t)(r7 << 1);
    uint32_t Bb2off = (uint32_t)((g2 * 8 + r7) * 256);

    float acc[2][8][4];
#pragma unroll
    for (int mt = 0; mt < 2; mt++)
#pragma unroll
        for (int nt = 0; nt < 8; nt++)
#pragma unroll
            for (int q = 0; q < 4; q++) acc[mt][nt][q] = 0.f;

    __syncthreads();   // wh2s staged

    for (int t = 0; t < CT; t++) {
        uint32_t Bbuf = sb + ((t & 1) ? B1o : B0o);
        asm volatile("cp.async.wait_group 0;");
        __syncthreads();   // B(t) visible; all warps done with B(t-1)'s buffer

        if (t + 1 < CT) {  // prefetch B(t+1)
            const char* src = bsrc + (t + 1) * 256;
            uint32_t dstb = sb + (((t + 1) & 1) ? B1o : B0o) + bdst_row;
#pragma unroll
            for (int k = 0; k < 4; k++)
                cp_async16(dstb + ((uint32_t)((bu0 + k) ^ bnx) << 4), src + k * 16);
            asm volatile("cp.async.commit_group;");
        }

#pragma unroll
        for (int ks = 0; ks < 8; ks++) {
            int kcg = t * 8 + ks;
            int b = ks & 1;
            // clamped prefetch offset (kc+2 wraps to 0 at the end; values unused)
            int kpf = (kcg + 2 < KCMAX) ? (kcg + 2) : 0;
            float4 wv = *(const float4*)(wh2s + t * 128 + ks * 16 + (lane & 3) * 4);

            uint32_t af[8];
#pragma unroll
            for (int s = 0; s < 4; s++) {
                int4 av = avv[b][s];
                float w1 = w1r[s], m2 = m2r[s];
                float s0 = w1 + wv.x, s1 = w1 + wv.y, s2 = w1 + wv.z, s3 = w1 + wv.w;
                float x0 = fmaf(fmaxf(s0, 0.2f * s0), LOG2E, -m2);
                float x1 = fmaf(fmaxf(s1, 0.2f * s1), LOG2E, -m2);
                float x2 = fmaf(fmaxf(s2, 0.2f * s2), LOG2E, -m2);
                float x3 = fmaf(fmaxf(s3, 0.2f * s3), LOG2E, -m2);
                x0 = av.x ? x0 : -1e4f;
                x1 = av.y ? x1 : -1e4f;
                x2 = av.z ? x2 : -1e4f;
                x3 = av.w ? x3 : -1e4f;
                avv[b][s] = __ldcs((const int4*)(pAdj + 8LL * s * NROW + kpf * 16));
                __half2 h01 = __floats2half2_rn(x0, x1);
                __half2 h23 = __floats2half2_rn(x2, x3);
                uint32_t e01, e23;
                asm("ex2.approx.f16x2 %0, %1;" : "=r"(e01) : "r"(*(uint32_t*)&h01));
                asm("ex2.approx.f16x2 %0, %1;" : "=r"(e23) : "r"(*(uint32_t*)&h23));
                // af slots: s0->(0,2) s1->(1,3) s2->(4,6) s3->(5,7)
                int lo = (s & 2) * 2 + (s & 1);
                af[lo] = e01;
                af[lo + 2] = e23;
                __half2 hs = __hadd2(*(__half2*)&e01, *(__half2*)&e23);
                float2 fs = __half22float2(hs);
                fr[s] += fs.x + fs.y;
            }

            uint32_t bsw = (((uint32_t)(ks * 2 + kh)) ^ bxor) << 4;
            uint32_t Bb = Bbuf + Bb2off + bsw;
#pragma unroll
            for (int nt2 = 0; nt2 < 4; nt2++) {
                uint32_t b0, b1, b2, b3;
                asm volatile("ldmatrix.sync.aligned.m8n8.x4.shared.b16 {%0,%1,%2,%3}, [%4];"
                             : "=r"(b0), "=r"(b1), "=r"(b2), "=r"(b3)
                             : "r"(Bb + (uint32_t)(nt2 * 4096)));
                int nt = nt2 * 2;
                asm volatile("mma.sync.aligned.m16n8k16.row.col.f32.f16.f16.f32 "
                             "{%0,%1,%2,%3}, {%4,%5,%6,%7}, {%8,%9}, {%0,%1,%2,%3};"
                             : "+f"(acc[0][nt][0]), "+f"(acc[0][nt][1]),
                               "+f"(acc[0][nt][2]), "+f"(acc[0][nt][3])
                             : "r"(af[0]), "r"(af[1]), "r"(af[2]), "r"(af[3]), "r"(b0), "r"(b1));
                asm volatile("mma.sync.aligned.m16n8k16.row.col.f32.f16.f16.f32 "
                             "{%0,%1,%2,%3}, {%4,%5,%6,%7}, {%8,%9}, {%0,%1,%2,%3};"
                             : "+f"(acc[0][nt + 1][0]), "+f"(acc[0][nt + 1][1]),
                               "+f"(acc[0][nt + 1][2]), "+f"(acc[0][nt + 1][3])
                             : "r"(af[0]), "r"(af[1]), "r"(af[2]), "r"(af[3]), "r"(b2), "r"(b3));
                asm volatile("mma.sync.aligned.m16n8k16.row.col.f32.f16.f16.f32 "
                             "{%0,%1,%2,%3}, {%4,%5,%6,%7}, {%8,%9}, {%0,%1,%2,%3};"
                             : "+f"(acc[1][nt][0]), "+f"(acc[1][nt][1]),
                               "+f"(acc[1][nt][2]), "+f"(acc[1][nt][3])
                             : "r"(af[4]), "r"(af[5]), "r"(af[6]), "r"(af[7]), "r"(b0), "r"(b1));
                asm volatile("mma.sync.aligned.m16n8k16.row.col.f32.f16.f16.f32 "
                             "{%0,%1,%2,%3}, {%4,%5,%6,%7}, {%8,%9}, {%0,%1,%2,%3};"
                             : "+f"(acc[1][nt + 1][0]), "+f"(acc[1][nt + 1][1]),
                               "+f"(acc[1][nt + 1][2]), "+f"(acc[1][nt + 1][3])
                             : "r"(af[4]), "r"(af[5]), "r"(af[6]), "r"(af[7]), "r"(b2), "r"(b3));
            }
        }
    }

    // ---------------- writeback ----------------
    {
        float* Sp = g_S[chunk];
        int g = lane >> 2, tq = lane & 3;
#pragma unroll
        for (int mt = 0; mt < 2; mt++)
#pragma unroll
            for (int nt = 0; nt < 8; nt++) {
                int row0 = i0 + w * 32 + mt * 16 + g;
                int col = nt * 8 + tq * 2;
                *(float2*)(Sp + row0 * OUTF + col) =
                    make_float2(acc[mt][nt][0], acc[mt][nt][1]);
                *(float2*)(Sp + (row0 + 8) * OUTF + col) =
                    make_float2(acc[mt][nt][2], acc[mt][nt][3]);
            }
    }
    // row sums: reduce within c-quad, write
#pragma unroll
    for (int s = 0; s < 4; s++) {
        fr[s] += __shfl_xor_sync(~0u, fr[s], 1);
        fr[s] += __shfl_xor_sync(~0u, fr[s], 2);
    }
    if ((lane & 3) == 0) {
#pragma unroll
        for (int s = 0; s < 4; s++)
            g_L[chunk][rA + 8 * s] = fr[s];
    }
}

// ---------------- Kernel C: reduce chunks, normalize + ELU ----------------
__global__ void kEpi(float* __restrict__ out) {
    int idx = blockIdx.x * 256 + threadIdx.x;   // NROW*64
    int i = idx >> 6, f = idx & 63;
    float l = 0.f, v = 0.f;
#pragma unroll
    for (int c = 0; c < NCHUNK; c++) {
        l += g_L[c][i];
        v += g_S[c][i * OUTF + f];
    }
    v /= l;
    out[idx] = v > 0.f ? v : expm1f(v);
}

// ---------------- launch ----------------
extern "C" void kernel_launch(void* const* d_in, const int* in_sizes, int n_in,
                              void* d_out, int out_size) {
    (void)in_sizes; (void)n_in; (void)out_size;
    const float* inp = (const float*)d_in[0];
    const int*   adj = (const int*)d_in[1];
    const float* W   = (const float*)d_in[2];
    const float* a   = (const float*)d_in[3];

    cudaFuncSetAttribute(kMain, cudaFuncAttributeMaxDynamicSharedMemorySize, SMEM_BYTES);

    kA<<<NROW / 4, 256>>>(inp, W, a);           // index 0
    kMax<<<1, 256>>>();                         // index 1
    kPad<<<1, 32>>>();                          // index 2
    kMain<<<NUNITS, 256, SMEM_BYTES>>>(adj);    // index 3  <- ncu capture
    kEpi<<<NROW * OUTF / 256, 256>>>((float*)d_out);
}